// round 11
// baseline (speedup 1.0000x reference)
#include <cuda_runtime.h>
#include <math.h>

// ---------------------------------------------------------------------------
// Fused NeRF MLP inference, fp32, packed f32x2 FMA (FFMA2) path.
// R10 evidence: 6680us, fma=62.2%, L1=82.4% -> staging + barriers + residual
// LDS co-binding with FMA.
// R11: TP=128/TPB=256 (one block/SM, staging amortized over 2x points),
//      float4 staging (LDG.128/STS.128, scalar fallback for 129-stride b2w3),
//      double-buffered s_w (1 barrier/chunk, LDG latency hidden).
// Mainloop (conflict-free tc*4+32q weight map, float2 acts) unchanged.
// ---------------------------------------------------------------------------

#define TPB 256
#define TP 128
#define LDH 130   // 4*130 % 32 == 8 -> tp rows on banks {0,8,16,24}
#define LDXE 66
#define LDDE 34

typedef unsigned long long u64;

__device__ __forceinline__ u64 pack2(float x, float y) {
    u64 r; asm("mov.b64 %0, {%1, %2};" : "=l"(r) : "f"(x), "f"(y)); return r;
}
__device__ __forceinline__ float2 unpack2(u64 v) {
    float2 r; asm("mov.b64 {%0, %1}, %2;" : "=f"(r.x), "=f"(r.y) : "l"(v)); return r;
}
__device__ __forceinline__ void ffma2(u64& d, u64 a, u64 b) {
    asm("fma.rn.f32x2 %0, %1, %2, %0;" : "+l"(d) : "l"(a), "l"(b));
}

// Accurate sin/cos via fp64 round-to-quadrant reduction + fp32 minimax.
__device__ __forceinline__ void sincos_accurate(double y, float& so, float& co) {
    double t = y * 0.63661977236758134308;     // 2/pi
    int q = __double2int_rn(t);
    float r = (float)__fma_rn(-(double)q, 1.5707963267948966, y);
    float z = r * r;
    float sp = fmaf(fmaf(-1.9515295891e-4f, z, 8.3321608736e-3f), z,
                    -1.6666654611e-1f);
    float ss = fmaf(r * z, sp, r);
    float cp = fmaf(fmaf(2.443315711809948e-5f, z, -1.388731625493765e-3f), z,
                    4.166664568298827e-2f);
    float cc = fmaf(z * z, cp, fmaf(-0.5f, z, 1.0f));
    int qm = q & 3;
    so = (qm == 0) ? ss : (qm == 1) ? cc : (qm == 2) ? -ss : -cc;
    co = (qm == 0) ? cc : (qm == 1) ? -ss : (qm == 2) ? -cc : ss;
}

// Stage one 32-row x NC chunk of gW (row stride g_ld) into s_w; rows >= K -> 0.
template <int NC, bool VEC>
__device__ __forceinline__ void stage_chunk(
    const float* __restrict__ gW, int K, int g_ld, int k0,
    float* __restrict__ s_w, int tid)
{
    if (VEC) {
        constexpr int NV = NC / 4;            // float4 per row
#pragma unroll
        for (int i = 0; i < (32 * NV) / TPB; ++i) {
            int idx = tid + i * TPB;
            int r = idx / NV;                 // NV pow2 -> shift
            int c4 = idx & (NV - 1);
            int krow = k0 + r;
            float4 v = make_float4(0.f, 0.f, 0.f, 0.f);
            if (krow < K)
                v = *reinterpret_cast<const float4*>(gW + krow * g_ld + c4 * 4);
            *reinterpret_cast<float4*>(s_w + r * NC + c4 * 4) = v;
        }
    } else {
#pragma unroll
        for (int i = 0; i < (32 * NC) / TPB; ++i) {
            int idx = tid + i * TPB;
            int r = idx / NC;
            int col = idx & (NC - 1);
            int krow = k0 + r;
            s_w[idx] = (krow < K) ? gW[krow * g_ld + col] : 0.0f;
        }
    }
}

// One 32-row K chunk. Thread handles cols {tc*4 + 32*q + 0..3 : q<Q}, Q=NC/32.
template <int NC>
__device__ __forceinline__ void acc_chunk32(
    const float* __restrict__ sA, int lda,
    const float* __restrict__ sW,
    u64* __restrict__ acc, int tp, int tc)
{
    constexpr int Q = NC / 32;
    constexpr int J = 2 * Q;
    const float* a0p = sA + (tp * 4 + 0) * lda;
    const float* a1p = sA + (tp * 4 + 1) * lda;
    const float* a2p = sA + (tp * 4 + 2) * lda;
    const float* a3p = sA + (tp * 4 + 3) * lda;
    const float* wp  = sW + tc * 4;
#pragma unroll
    for (int k2 = 0; k2 < 16; ++k2) {
        float2 a0 = *reinterpret_cast<const float2*>(a0p + 2 * k2);
        float2 a1 = *reinterpret_cast<const float2*>(a1p + 2 * k2);
        float2 a2 = *reinterpret_cast<const float2*>(a2p + 2 * k2);
        float2 a3 = *reinterpret_cast<const float2*>(a3p + 2 * k2);
#pragma unroll
        for (int h = 0; h < 2; ++h) {
            int k = 2 * k2 + h;
            float v0 = h ? a0.y : a0.x;
            float v1 = h ? a1.y : a1.x;
            float v2 = h ? a2.y : a2.x;
            float v3 = h ? a3.y : a3.x;
            u64 pa0 = pack2(v0, v0);
            u64 pa1 = pack2(v1, v1);
            u64 pa2 = pack2(v2, v2);
            u64 pa3 = pack2(v3, v3);
            u64 w[J];
#pragma unroll
            for (int q = 0; q < Q; ++q) {
                ulonglong2 qv = *reinterpret_cast<const ulonglong2*>(
                    wp + k * NC + q * 32);
                w[2 * q]     = qv.x;
                w[2 * q + 1] = qv.y;
            }
#pragma unroll
            for (int j = 0; j < J; ++j) ffma2(acc[0 * J + j], pa0, w[j]);
#pragma unroll
            for (int j = 0; j < J; ++j) ffma2(acc[1 * J + j], pa1, w[j]);
#pragma unroll
            for (int j = 0; j < J; ++j) ffma2(acc[2 * J + j], pa2, w[j]);
#pragma unroll
            for (int j = 0; j < J; ++j) ffma2(acc[3 * J + j], pa3, w[j]);
        }
    }
}

// One layer: sOut[TP][NC] = act( [sA1 | sA2][TP][K] @ gW[K][NC] )
// Double-buffered weight staging: one barrier per chunk, LDG under compute.
template <bool RELU, int NC, bool VEC>
__device__ __noinline__ void gemm_layer(
    const float* __restrict__ gW, int K, int g_ld,
    const float* __restrict__ sA1, int lda1, int K1,
    const float* __restrict__ sA2, int lda2,
    float* __restrict__ sOut, int ldo,
    float* __restrict__ s_wA, float* __restrict__ s_wB,
    int tid, int tp, int tc)
{
    constexpr int Q = NC / 32;
    constexpr int J = 2 * Q;
    u64 acc[4 * J];
#pragma unroll
    for (int i = 0; i < 4 * J; ++i) acc[i] = 0ull;

    const int nch = (K + 31) >> 5;
    stage_chunk<NC, VEC>(gW, K, g_ld, 0, s_wA, tid);
    __syncthreads();   // s_wA ready; also orders prev-layer activation stores
    for (int c = 0; c < nch; ++c) {
        float* cur = (c & 1) ? s_wB : s_wA;
        float* nxt = (c & 1) ? s_wA : s_wB;
        if (c + 1 < nch)
            stage_chunk<NC, VEC>(gW, K, g_ld, (c + 1) * 32, nxt, tid);
        int k0 = c * 32;
        if (k0 < K1) acc_chunk32<NC>(sA1 + k0, lda1, cur, acc, tp, tc);
        else         acc_chunk32<NC>(sA2 + (k0 - K1), lda2, cur, acc, tp, tc);
        __syncthreads();  // nxt fully staged + cur fully consumed
    }
#pragma unroll
    for (int i = 0; i < 4; ++i) {
        float* orow = sOut + (tp * 4 + i) * ldo + tc * 4;
#pragma unroll
        for (int q = 0; q < Q; ++q) {
#pragma unroll
            for (int h = 0; h < 2; ++h) {
                float2 v = unpack2(acc[i * J + 2 * q + h]);
                if (RELU) { v.x = fmaxf(v.x, 0.0f); v.y = fmaxf(v.y, 0.0f); }
                *reinterpret_cast<float2*>(orow + q * 32 + h * 2) = v;
            }
        }
    }
}

extern __shared__ float smem[];

__global__ __launch_bounds__(TPB, 1) void nerf_fused_kernel(
    const float* __restrict__ pos, const float* __restrict__ dirs,
    const float* __restrict__ b1w0, const float* __restrict__ b1w1,
    const float* __restrict__ b1w2, const float* __restrict__ b1w3,
    const float* __restrict__ b1w4,
    const float* __restrict__ b2w0, const float* __restrict__ b2w1,
    const float* __restrict__ b2w2, const float* __restrict__ b2w3,
    const float* __restrict__ b3w0, const float* __restrict__ b3w1,
    float* __restrict__ out, int N)
{
    float* s_wA  = smem;                        // 32*128
    float* s_wB  = s_wA + 32 * 128;             // 32*128
    float* s_xe  = s_wB + 32 * 128;             // 128*66
    float* s_de  = s_xe + TP * LDXE;            // 128*34
    float* s_h0  = s_de + TP * LDDE;            // 128*130
    float* s_h1  = s_h0 + TP * LDH;             // 128*130
    float* s_tmp = s_h1 + TP * LDH;             // 256

    const int tid = threadIdx.x;
    const int tc = tid & 7;
    const int tp = tid >> 3;                    // 0..31
    const int pbase = blockIdx.x * TP;

    // Zero pad tails (garbage x zero-weight could be NaN on first run)
    for (int p = tid; p < TP; p += TPB) {
#pragma unroll
        for (int m = 63; m < LDXE; ++m) s_xe[p * LDXE + m] = 0.0f;
#pragma unroll
        for (int m = 27; m < LDDE; ++m) s_de[p * LDDE + m] = 0.0f;
    }

    // ---- positional encodings: exact per-frequency reduction ----
    for (int t = tid; t < TP * 3; t += TPB) {
        int p = t / 3, cd = t - p * 3;
        int pg = pbase + p;
        float xp = (pg < N) ? pos[pg * 3 + cd]  : 0.0f;
        float xd = (pg < N) ? dirs[pg * 3 + cd] : 0.0f;

        float* xe = s_xe + p * LDXE;
        xe[cd] = xp;
        {
            double y = (double)xp;
#pragma unroll
            for (int j = 0; j < 10; ++j) {
                float s, c;
                sincos_accurate(y, s, c);
                xe[3 + 6 * j + cd]     = s;
                xe[3 + 6 * j + 3 + cd] = c;
                y += y;
            }
        }
        float* de = s_de + p * LDDE;
        de[cd] = xd;
        {
            double y = (double)xd;
#pragma unroll
            for (int j = 0; j < 4; ++j) {
                float s, c;
                sincos_accurate(y, s, c);
                de[3 + 6 * j + cd]     = s;
                de[3 + 6 * j + 3 + cd] = c;
                y += y;
            }
        }
    }
    // (first __syncthreads inside gemm_layer orders these writes)

    const int BIG = 1 << 30;  // "no concat" sentinel

    // ---- block 1: 63->128, 4x 128->128, all relu ----
    gemm_layer<true,128,true>(b1w0,  63, 128, s_xe, LDXE, BIG, nullptr, 0, s_h0, LDH, s_wA, s_wB, tid, tp, tc);
    gemm_layer<true,128,true>(b1w1, 128, 128, s_h0, LDH,  BIG, nullptr, 0, s_h1, LDH, s_wA, s_wB, tid, tp, tc);
    gemm_layer<true,128,true>(b1w2, 128, 128, s_h1, LDH,  BIG, nullptr, 0, s_h0, LDH, s_wA, s_wB, tid, tp, tc);
    gemm_layer<true,128,true>(b1w3, 128, 128, s_h0, LDH,  BIG, nullptr, 0, s_h1, LDH, s_wA, s_wB, tid, tp, tc);
    gemm_layer<true,128,true>(b1w4, 128, 128, s_h1, LDH,  BIG, nullptr, 0, s_h0, LDH, s_wA, s_wB, tid, tp, tc);

    // ---- block 2: concat(h, x_emb)=191 -> 128, 2x 128->128 relu, 128->129 ----
    gemm_layer<true,128,true>(b2w0, 191, 128, s_h0, LDH, 128, s_xe, LDXE, s_h1, LDH, s_wA, s_wB, tid, tp, tc);
    gemm_layer<true,128,true>(b2w1, 128, 128, s_h1, LDH,  BIG, nullptr, 0, s_h0, LDH, s_wA, s_wB, tid, tp, tc);
    gemm_layer<true,128,true>(b2w2, 128, 128, s_h0, LDH,  BIG, nullptr, 0, s_h1, LDH, s_wA, s_wB, tid, tp, tc);
    // feat = first 128 cols (no relu); g_in stays in s_h1 for the sigma dot
    // g_ld=129 not float4-aligned -> scalar staging
    gemm_layer<false,128,false>(b2w3, 128, 129, s_h1, LDH, BIG, nullptr, 0, s_h0, LDH, s_wA, s_wB, tid, tp, tc);

    // ---- sigma: col 128 of b2w3, relu ----
    __syncthreads();
    if (tid < 128) s_tmp[tid] = b2w3[tid * 129 + 128];
    __syncthreads();
    if (tid < TP) {
        const float* g = s_h1 + tid * LDH;
        float acc = 0.0f;
#pragma unroll 16
        for (int k = 0; k < 128; ++k) acc += g[k] * s_tmp[k];
        int pg = pbase + tid;
        if (pg < N) out[3 * N + pg] = fmaxf(acc, 0.0f);
    }

    // ---- block 3: concat(feat, d_emb)=155 -> 64 relu ----
    gemm_layer<true,64,true>(b3w0, 155, 64, s_h0, LDH, 128, s_de, LDDE, s_h1, LDH, s_wA, s_wB, tid, tp, tc);

    // ---- color head: [64,3] + sigmoid ----
    __syncthreads();
    for (int i = tid; i < 192; i += TPB) s_tmp[i] = b3w1[i];
    __syncthreads();
    if (tid < TP) {
        const float* h = s_h1 + tid * LDH;
        float r0 = 0.0f, r1 = 0.0f, r2 = 0.0f;
#pragma unroll 16
        for (int k = 0; k < 64; ++k) {
            float a = h[k];
            r0 += a * s_tmp[k * 3 + 0];
            r1 += a * s_tmp[k * 3 + 1];
            r2 += a * s_tmp[k * 3 + 2];
        }
        r0 = 1.0f / (1.0f + __expf(-r0));
        r1 = 1.0f / (1.0f + __expf(-r1));
        r2 = 1.0f / (1.0f + __expf(-r2));
        int pg = pbase + tid;
        if (pg < N) {
            out[pg * 3 + 0] = r0;
            out[pg * 3 + 1] = r1;
            out[pg * 3 + 2] = r2;
        }
    }
}

extern "C" void kernel_launch(void* const* d_in, const int* in_sizes, int n_in,
                              void* d_out, int out_size)
{
    const float* pos  = (const float*)d_in[0];
    const float* dirs = (const float*)d_in[1];
    const float* b1w0 = (const float*)d_in[2];
    const float* b1w1 = (const float*)d_in[3];
    const float* b1w2 = (const float*)d_in[4];
    const float* b1w3 = (const float*)d_in[5];
    const float* b1w4 = (const float*)d_in[6];
    const float* b2w0 = (const float*)d_in[7];
    const float* b2w1 = (const float*)d_in[8];
    const float* b2w2 = (const float*)d_in[9];
    const float* b2w3 = (const float*)d_in[10];
    const float* b3w0 = (const float*)d_in[11];
    const float* b3w1 = (const float*)d_in[12];
    float* out = (float*)d_out;

    int N = in_sizes[0] / 3;

    const int smem_bytes =
        (2 * 32 * 128 + TP * LDXE + TP * LDDE + 2 * TP * LDH + 256) *
        (int)sizeof(float);
    cudaFuncSetAttribute(nerf_fused_kernel,
                         cudaFuncAttributeMaxDynamicSharedMemorySize, smem_bytes);

    int blocks = (N + TP - 1) / TP;
    nerf_fused_kernel<<<blocks, TPB, smem_bytes>>>(
        pos, dirs, b1w0, b1w1, b1w2, b1w3, b1w4,
        b2w0, b2w1, b2w2, b2w3, b3w0, b3w1, out, N);
}

// round 13
// speedup vs baseline: 1.0740x; 1.0740x over previous
#include <cuda_runtime.h>
#include <math.h>

// ---------------------------------------------------------------------------
// Fused NeRF MLP inference, fp32, packed f32x2 FMA (FFMA2) path.
// R10: 6680us (fma 62.2%, L1 82.4%) with TPB=128/TP=64, 2 blocks/SM.
// R11: TPB=256/1 block/SM + double-buffer REGRESSED to 7062us: fma 58.4% --
//   single-block barriers idle the whole SM; 2-block overlap was load-bearing.
// R12: revert to R10 config, keep only the SMEM-free R11 win: float4 staging
//   (LDG.128/STS.128; scalar fallback for b2w3's 129 stride). Numerics
//   identical to R10. R12 resubmit (GPU timeout).
// ---------------------------------------------------------------------------

#define TPB 128
#define TP 64
#define LDH 130   // 4*130 % 32 == 8 -> tp rows on banks {0,8,16,24}
#define LDXE 66
#define LDDE 34

typedef unsigned long long u64;

__device__ __forceinline__ u64 pack2(float x, float y) {
    u64 r; asm("mov.b64 %0, {%1, %2};" : "=l"(r) : "f"(x), "f"(y)); return r;
}
__device__ __forceinline__ float2 unpack2(u64 v) {
    float2 r; asm("mov.b64 {%0, %1}, %2;" : "=f"(r.x), "=f"(r.y) : "l"(v)); return r;
}
__device__ __forceinline__ void ffma2(u64& d, u64 a, u64 b) {
    asm("fma.rn.f32x2 %0, %1, %2, %0;" : "+l"(d) : "l"(a), "l"(b));
}

// Accurate sin/cos via fp64 round-to-quadrant reduction + fp32 minimax.
__device__ __forceinline__ void sincos_accurate(double y, float& so, float& co) {
    double t = y * 0.63661977236758134308;     // 2/pi
    int q = __double2int_rn(t);
    float r = (float)__fma_rn(-(double)q, 1.5707963267948966, y);
    float z = r * r;
    float sp = fmaf(fmaf(-1.9515295891e-4f, z, 8.3321608736e-3f), z,
                    -1.6666654611e-1f);
    float ss = fmaf(r * z, sp, r);
    float cp = fmaf(fmaf(2.443315711809948e-5f, z, -1.388731625493765e-3f), z,
                    4.166664568298827e-2f);
    float cc = fmaf(z * z, cp, fmaf(-0.5f, z, 1.0f));
    int qm = q & 3;
    so = (qm == 0) ? ss : (qm == 1) ? cc : (qm == 2) ? -ss : -cc;
    co = (qm == 0) ? cc : (qm == 1) ? -ss : (qm == 2) ? -cc : ss;
}

// Stage one 32-row x NC chunk of gW (row stride g_ld) into s_w; rows >= K -> 0.
template <int NC, bool VEC>
__device__ __forceinline__ void stage_chunk(
    const float* __restrict__ gW, int K, int g_ld, int k0,
    float* __restrict__ s_w, int tid)
{
    if (VEC) {
        constexpr int NV = NC / 4;            // float4 per row
#pragma unroll
        for (int i = 0; i < (32 * NV) / TPB; ++i) {
            int idx = tid + i * TPB;
            int r = idx / NV;                 // NV pow2 -> shift
            int c4 = idx & (NV - 1);
            int krow = k0 + r;
            float4 v = make_float4(0.f, 0.f, 0.f, 0.f);
            if (krow < K)
                v = *reinterpret_cast<const float4*>(gW + krow * g_ld + c4 * 4);
            *reinterpret_cast<float4*>(s_w + r * NC + c4 * 4) = v;
        }
    } else {
#pragma unroll
        for (int i = 0; i < (32 * NC) / TPB; ++i) {
            int idx = tid + i * TPB;
            int r = idx / NC;
            int col = idx & (NC - 1);
            int krow = k0 + r;
            s_w[idx] = (krow < K) ? gW[krow * g_ld + col] : 0.0f;
        }
    }
}

// One 32-row K chunk. Thread handles cols {tc*4 + 32*q + 0..3 : q<Q}, Q=NC/32.
template <int NC>
__device__ __forceinline__ void acc_chunk32(
    const float* __restrict__ sA, int lda,
    const float* __restrict__ sW,
    u64* __restrict__ acc, int tp, int tc)
{
    constexpr int Q = NC / 32;
    constexpr int J = 2 * Q;
    const float* a0p = sA + (tp * 4 + 0) * lda;
    const float* a1p = sA + (tp * 4 + 1) * lda;
    const float* a2p = sA + (tp * 4 + 2) * lda;
    const float* a3p = sA + (tp * 4 + 3) * lda;
    const float* wp  = sW + tc * 4;
#pragma unroll
    for (int k2 = 0; k2 < 16; ++k2) {
        float2 a0 = *reinterpret_cast<const float2*>(a0p + 2 * k2);
        float2 a1 = *reinterpret_cast<const float2*>(a1p + 2 * k2);
        float2 a2 = *reinterpret_cast<const float2*>(a2p + 2 * k2);
        float2 a3 = *reinterpret_cast<const float2*>(a3p + 2 * k2);
#pragma unroll
        for (int h = 0; h < 2; ++h) {
            int k = 2 * k2 + h;
            float v0 = h ? a0.y : a0.x;
            float v1 = h ? a1.y : a1.x;
            float v2 = h ? a2.y : a2.x;
            float v3 = h ? a3.y : a3.x;
            u64 pa0 = pack2(v0, v0);
            u64 pa1 = pack2(v1, v1);
            u64 pa2 = pack2(v2, v2);
            u64 pa3 = pack2(v3, v3);
            u64 w[J];
#pragma unroll
            for (int q = 0; q < Q; ++q) {
                ulonglong2 qv = *reinterpret_cast<const ulonglong2*>(
                    wp + k * NC + q * 32);
                w[2 * q]     = qv.x;
                w[2 * q + 1] = qv.y;
            }
#pragma unroll
            for (int j = 0; j < J; ++j) ffma2(acc[0 * J + j], pa0, w[j]);
#pragma unroll
            for (int j = 0; j < J; ++j) ffma2(acc[1 * J + j], pa1, w[j]);
#pragma unroll
            for (int j = 0; j < J; ++j) ffma2(acc[2 * J + j], pa2, w[j]);
#pragma unroll
            for (int j = 0; j < J; ++j) ffma2(acc[3 * J + j], pa3, w[j]);
        }
    }
}

// One layer: sOut[TP][NC] = act( [sA1 | sA2][TP][K] @ gW[K][NC] )
template <bool RELU, int NC, bool VEC>
__device__ __noinline__ void gemm_layer(
    const float* __restrict__ gW, int K, int g_ld,
    const float* __restrict__ sA1, int lda1, int K1,
    const float* __restrict__ sA2, int lda2,
    float* __restrict__ sOut, int ldo,
    float* __restrict__ s_w, int tid, int tp, int tc)
{
    constexpr int Q = NC / 32;
    constexpr int J = 2 * Q;
    u64 acc[4 * J];
#pragma unroll
    for (int i = 0; i < 4 * J; ++i) acc[i] = 0ull;

    const int nch = (K + 31) >> 5;
    for (int c = 0; c < nch; ++c) {
        int k0 = c * 32;
        __syncthreads();  // protect s_w reuse; orders prev-layer stores
        stage_chunk<NC, VEC>(gW, K, g_ld, k0, s_w, tid);
        __syncthreads();
        if (k0 < K1) acc_chunk32<NC>(sA1 + k0, lda1, s_w, acc, tp, tc);
        else         acc_chunk32<NC>(sA2 + (k0 - K1), lda2, s_w, acc, tp, tc);
    }
#pragma unroll
    for (int i = 0; i < 4; ++i) {
        float* orow = sOut + (tp * 4 + i) * ldo + tc * 4;
#pragma unroll
        for (int q = 0; q < Q; ++q) {
#pragma unroll
            for (int h = 0; h < 2; ++h) {
                float2 v = unpack2(acc[i * J + 2 * q + h]);
                if (RELU) { v.x = fmaxf(v.x, 0.0f); v.y = fmaxf(v.y, 0.0f); }
                *reinterpret_cast<float2*>(orow + q * 32 + h * 2) = v;
            }
        }
    }
}

extern __shared__ float smem[];

__global__ __launch_bounds__(TPB, 2) void nerf_fused_kernel(
    const float* __restrict__ pos, const float* __restrict__ dirs,
    const float* __restrict__ b1w0, const float* __restrict__ b1w1,
    const float* __restrict__ b1w2, const float* __restrict__ b1w3,
    const float* __restrict__ b1w4,
    const float* __restrict__ b2w0, const float* __restrict__ b2w1,
    const float* __restrict__ b2w2, const float* __restrict__ b2w3,
    const float* __restrict__ b3w0, const float* __restrict__ b3w1,
    float* __restrict__ out, int N)
{
    float* s_w   = smem;                       // 32*128
    float* s_xe  = s_w  + 32 * 128;            // 64*66
    float* s_de  = s_xe + TP * LDXE;           // 64*34
    float* s_h0  = s_de + TP * LDDE;           // 64*130
    float* s_h1  = s_h0 + TP * LDH;            // 64*130
    float* s_tmp = s_h1 + TP * LDH;            // 256

    const int tid = threadIdx.x;
    const int tc = tid & 7;
    const int tp = tid >> 3;
    const int pbase = blockIdx.x * TP;

    // Zero pad tails (garbage x zero-weight could be NaN on first run)
    for (int p = tid; p < TP; p += TPB) {
#pragma unroll
        for (int m = 63; m < LDXE; ++m) s_xe[p * LDXE + m] = 0.0f;
#pragma unroll
        for (int m = 27; m < LDDE; ++m) s_de[p * LDDE + m] = 0.0f;
    }

    // ---- positional encodings: exact per-frequency reduction ----
    for (int t = tid; t < TP * 3; t += TPB) {
        int p = t / 3, cd = t - p * 3;
        int pg = pbase + p;
        float xp = (pg < N) ? pos[pg * 3 + cd]  : 0.0f;
        float xd = (pg < N) ? dirs[pg * 3 + cd] : 0.0f;

        float* xe = s_xe + p * LDXE;
        xe[cd] = xp;
        {
            double y = (double)xp;
#pragma unroll
            for (int j = 0; j < 10; ++j) {
                float s, c;
                sincos_accurate(y, s, c);
                xe[3 + 6 * j + cd]     = s;
                xe[3 + 6 * j + 3 + cd] = c;
                y += y;
            }
        }
        float* de = s_de + p * LDDE;
        de[cd] = xd;
        {
            double y = (double)xd;
#pragma unroll
            for (int j = 0; j < 4; ++j) {
                float s, c;
                sincos_accurate(y, s, c);
                de[3 + 6 * j + cd]     = s;
                de[3 + 6 * j + 3 + cd] = c;
                y += y;
            }
        }
    }
    // (first __syncthreads inside gemm_layer orders these writes)

    const int BIG = 1 << 30;  // "no concat" sentinel

    // ---- block 1: 63->128, 4x 128->128, all relu ----
    gemm_layer<true,128,true>(b1w0,  63, 128, s_xe, LDXE, BIG, nullptr, 0, s_h0, LDH, s_w, tid, tp, tc);
    gemm_layer<true,128,true>(b1w1, 128, 128, s_h0, LDH,  BIG, nullptr, 0, s_h1, LDH, s_w, tid, tp, tc);
    gemm_layer<true,128,true>(b1w2, 128, 128, s_h1, LDH,  BIG, nullptr, 0, s_h0, LDH, s_w, tid, tp, tc);
    gemm_layer<true,128,true>(b1w3, 128, 128, s_h0, LDH,  BIG, nullptr, 0, s_h1, LDH, s_w, tid, tp, tc);
    gemm_layer<true,128,true>(b1w4, 128, 128, s_h1, LDH,  BIG, nullptr, 0, s_h0, LDH, s_w, tid, tp, tc);

    // ---- block 2: concat(h, x_emb)=191 -> 128, 2x 128->128 relu, 128->129 ----
    gemm_layer<true,128,true>(b2w0, 191, 128, s_h0, LDH, 128, s_xe, LDXE, s_h1, LDH, s_w, tid, tp, tc);
    gemm_layer<true,128,true>(b2w1, 128, 128, s_h1, LDH,  BIG, nullptr, 0, s_h0, LDH, s_w, tid, tp, tc);
    gemm_layer<true,128,true>(b2w2, 128, 128, s_h0, LDH,  BIG, nullptr, 0, s_h1, LDH, s_w, tid, tp, tc);
    // feat = first 128 cols (no relu); g_ld=129 not 16B-aligned -> scalar stage
    gemm_layer<false,128,false>(b2w3, 128, 129, s_h1, LDH, BIG, nullptr, 0, s_h0, LDH, s_w, tid, tp, tc);

    // ---- sigma: col 128 of b2w3, relu ----
    __syncthreads();
    if (tid < 128) s_tmp[tid] = b2w3[tid * 129 + 128];
    __syncthreads();
    if (tid < TP) {
        const float* g = s_h1 + tid * LDH;
        float acc = 0.0f;
#pragma unroll 16
        for (int k = 0; k < 128; ++k) acc += g[k] * s_tmp[k];
        int pg = pbase + tid;
        if (pg < N) out[3 * N + pg] = fmaxf(acc, 0.0f);
    }

    // ---- block 3: concat(feat, d_emb)=155 -> 64 relu ----
    gemm_layer<true,64,true>(b3w0, 155, 64, s_h0, LDH, 128, s_de, LDDE, s_h1, LDH, s_w, tid, tp, tc);

    // ---- color head: [64,3] + sigmoid ----
    __syncthreads();
    for (int i = tid; i < 192; i += TPB) s_tmp[i] = b3w1[i];
    __syncthreads();
    if (tid < TP) {
        const float* h = s_h1 + tid * LDH;
        float r0 = 0.0f, r1 = 0.0f, r2 = 0.0f;
#pragma unroll 16
        for (int k = 0; k < 64; ++k) {
            float a = h[k];
            r0 += a * s_tmp[k * 3 + 0];
            r1 += a * s_tmp[k * 3 + 1];
            r2 += a * s_tmp[k * 3 + 2];
        }
        r0 = 1.0f / (1.0f + __expf(-r0));
        r1 = 1.0f / (1.0f + __expf(-r1));
        r2 = 1.0f / (1.0f + __expf(-r2));
        int pg = pbase + tid;
        if (pg < N) {
            out[pg * 3 + 0] = r0;
            out[pg * 3 + 1] = r1;
            out[pg * 3 + 2] = r2;
        }
    }
}

extern "C" void kernel_launch(void* const* d_in, const int* in_sizes, int n_in,
                              void* d_out, int out_size)
{
    const float* pos  = (const float*)d_in[0];
    const float* dirs = (const float*)d_in[1];
    const float* b1w0 = (const float*)d_in[2];
    const float* b1w1 = (const float*)d_in[3];
    const float* b1w2 = (const float*)d_in[4];
    const float* b1w3 = (const float*)d_in[5];
    const float* b1w4 = (const float*)d_in[6];
    const float* b2w0 = (const float*)d_in[7];
    const float* b2w1 = (const float*)d_in[8];
    const float* b2w2 = (const float*)d_in[9];
    const float* b2w3 = (const float*)d_in[10];
    const float* b3w0 = (const float*)d_in[11];
    const float* b3w1 = (const float*)d_in[12];
    float* out = (float*)d_out;

    int N = in_sizes[0] / 3;

    const int smem_bytes =
        (32 * 128 + TP * LDXE + TP * LDDE + 2 * TP * LDH + 256) *
        (int)sizeof(float);
    cudaFuncSetAttribute(nerf_fused_kernel,
                         cudaFuncAttributeMaxDynamicSharedMemorySize, smem_bytes);

    int blocks = (N + TP - 1) / TP;
    nerf_fused_kernel<<<blocks, TPB, smem_bytes>>>(
        pos, dirs, b1w0, b1w1, b1w2, b1w3, b1w4,
        b2w0, b2w1, b2w2, b2w3, b3w0, b3w1, out, N);
}